// round 1
// baseline (speedup 1.0000x reference)
#include <cuda_runtime.h>

#define B 8
#define NPTS 2048
#define NTOT (B*NPTS)
#define LOGW 7.6246189861593985f   /* ln(2048) */
#define LOG2E 1.4426950408889634f
#define LN2 0.6931471805599453f

__device__ float4 d_X4[NTOT];
__device__ float4 d_Y4[NTOT];
__device__ float d_pots[2][4][NTOT];   // [buffer][f,g,fx,gy][b*N+i]

__device__ __forceinline__ float ex2(float x){ float r; asm("ex2.approx.ftz.f32 %0, %1;":"=f"(r):"f"(x)); return r; }
__device__ __forceinline__ float lg2(float x){ float r; asm("lg2.approx.f32 %0, %1;":"=f"(r):"f"(x)); return r; }

__global__ void prep_kernel(const float* __restrict__ p1, const float* __restrict__ p2) {
    int idx = blockIdx.x * blockDim.x + threadIdx.x;
    if (idx >= NTOT) return;
    float x = p1[3*idx], y = p1[3*idx+1], z = p1[3*idx+2];
    d_X4[idx] = make_float4(x, y, z, 0.5f*(x*x + y*y + z*z));
    x = p2[3*idx]; y = p2[3*idx+1]; z = p2[3*idx+2];
    d_Y4[idx] = make_float4(x, y, z, 0.5f*(x*x + y*y + z*z));
    d_pots[0][0][idx] = 0.f; d_pots[0][1][idx] = 0.f;
    d_pots[0][2][idx] = 0.f; d_pots[0][3][idx] = 0.f;
}

#define RPW 4          // rows per warp
#define WARPS 8
#define RPB (RPW*WARPS) // 32 rows per block

// One block: (task, batch, row-tile). Computes softmin rows for one of the
// four potential updates. Two-pass LSE with column tile (coords + shifted
// potential) staged in shared memory.
//   t_ij = (h_j - 0.5|y_j|^2 - eps*logw) + x_i . y_j       (natural units)
//   softmin_i = 0.5|x_i|^2 - m_i - eps * ln( sum_j exp((t_ij - m_i)/eps) )
__global__ __launch_bounds__(256) void iter_kernel(float eps, int inbuf, int avg) {
    __shared__ float4 sh[NPTS];
    int task = blockIdx.z, b = blockIdx.y;
    int ob = inbuf ^ 1;
    const float4* rows; const float4* cols;
    const float* colpot; const float* rowold; float* outp;
    if (task == 0)      { rows = d_X4; cols = d_Y4; colpot = d_pots[inbuf][1]; rowold = d_pots[inbuf][0]; outp = d_pots[ob][0]; }
    else if (task == 1) { rows = d_Y4; cols = d_X4; colpot = d_pots[inbuf][0]; rowold = d_pots[inbuf][1]; outp = d_pots[ob][1]; }
    else if (task == 2) { rows = d_X4; cols = d_X4; colpot = d_pots[inbuf][2]; rowold = d_pots[inbuf][2]; outp = d_pots[ob][2]; }
    else                { rows = d_Y4; cols = d_Y4; colpot = d_pots[inbuf][3]; rowold = d_pots[inbuf][3]; outp = d_pots[ob][3]; }
    rows += b*NPTS; cols += b*NPTS; colpot += b*NPTS; rowold += b*NPTS; outp += b*NPTS;

    float eps_logw = eps * LOGW;
    for (int j = threadIdx.x; j < NPTS; j += blockDim.x) {
        float4 c = cols[j];
        sh[j] = make_float4(c.x, c.y, c.z, colpot[j] - c.w - eps_logw);
    }
    __syncthreads();

    int warp = threadIdx.x >> 5, lane = threadIdx.x & 31;
    int row0 = blockIdx.x * RPB + warp * RPW;
    float4 xr[RPW];
#pragma unroll
    for (int r = 0; r < RPW; r++) xr[r] = rows[row0 + r];

    // pass 1: row max
    float m[RPW];
#pragma unroll
    for (int r = 0; r < RPW; r++) m[r] = -3.4e38f;
#pragma unroll 4
    for (int j = lane; j < NPTS; j += 32) {
        float4 c = sh[j];
#pragma unroll
        for (int r = 0; r < RPW; r++) {
            float t = fmaf(xr[r].x, c.x, fmaf(xr[r].y, c.y, fmaf(xr[r].z, c.z, c.w)));
            m[r] = fmaxf(m[r], t);
        }
    }
#pragma unroll
    for (int off = 16; off; off >>= 1)
#pragma unroll
        for (int r = 0; r < RPW; r++)
            m[r] = fmaxf(m[r], __shfl_xor_sync(0xffffffffu, m[r], off));

    // pass 2: sum of exp
    float kk = LOG2E / eps;
    float s[RPW];
#pragma unroll
    for (int r = 0; r < RPW; r++) s[r] = 0.f;
#pragma unroll 4
    for (int j = lane; j < NPTS; j += 32) {
        float4 c = sh[j];
#pragma unroll
        for (int r = 0; r < RPW; r++) {
            float t = fmaf(xr[r].x, c.x, fmaf(xr[r].y, c.y, fmaf(xr[r].z, c.z, c.w)));
            s[r] += ex2((t - m[r]) * kk);
        }
    }
#pragma unroll
    for (int off = 16; off; off >>= 1)
#pragma unroll
        for (int r = 0; r < RPW; r++)
            s[r] += __shfl_xor_sync(0xffffffffu, s[r], off);

    if (lane < RPW) {
        int r = lane;
        int row = row0 + r;
        float sm = xr[r].w - m[r] - eps * (lg2(s[r]) * LN2);
        outp[row] = avg ? 0.5f * (rowold[row] + sm) : sm;
    }
}

__global__ void reduce_kernel(int buf, float* __restrict__ out) {
    __shared__ float red[256];
    float acc = 0.f;
    for (int i = threadIdx.x; i < NTOT; i += 256) {
        acc += (d_pots[buf][0][i] - d_pots[buf][2][i])
             + (d_pots[buf][1][i] - d_pots[buf][3][i]);
    }
    red[threadIdx.x] = acc;
    __syncthreads();
    for (int off = 128; off; off >>= 1) {
        if (threadIdx.x < off) red[threadIdx.x] += red[threadIdx.x + off];
        __syncthreads();
    }
    if (threadIdx.x == 0) out[0] = red[0] / (float)NTOT;
}

extern "C" void kernel_launch(void* const* d_in, const int* in_sizes, int n_in,
                              void* d_out, int out_size) {
    const float* p1 = (const float*)d_in[0];
    const float* p2 = (const float*)d_in[1];
    float* out = (float*)d_out;

    // epsilon schedule: anneal in f64 (python-float semantics), square in f32
    float eps[128]; int n = 0;
    double sc = 8.0;
    while (sc > 0.01 && n < 120) { float f = (float)sc; eps[n++] = f * f; sc *= 0.9; }
    { float f = 0.01f; eps[n++] = f * f; }

    prep_kernel<<<(NTOT + 255) / 256, 256>>>(p1, p2);

    int inbuf = 0;
    dim3 grid(NPTS / RPB, B, 4);
    for (int k = 0; k < n; k++) {
        iter_kernel<<<grid, 256>>>(eps[k], inbuf, 1);
        inbuf ^= 1;
    }
    // final extrapolation at target eps, no averaging
    iter_kernel<<<grid, 256>>>(eps[n - 1], inbuf, 0);
    reduce_kernel<<<1, 256>>>(inbuf ^ 1, out);
}

// round 2
// speedup vs baseline: 1.1405x; 1.1405x over previous
#include <cuda_runtime.h>

#define B 8
#define NPTS 2048
#define NPAIR (NPTS/2)
#define NTOT (B*NPTS)
#define LOGW 7.6246189861593985f   /* ln(2048) */
#define LOG2E 1.4426950408889634f
#define LN2 0.6931471805599453f

typedef unsigned long long u64;

__device__ float4 d_X4[NTOT];              // per-row coords (x,y,z, 0.5|p|^2)
__device__ float4 d_Y4[NTOT];
__device__ float4 d_cA[2][NTOT/2];         // pair-packed cols: (x0,x1,y0,y1)
__device__ float4 d_cB[2][NTOT/2];         // pair-packed cols: (z0,z1,-w0,-w1)
__device__ float d_pots[2][4][NTOT];       // [buffer][f,g,fx,gy][b*N+i]

__device__ __forceinline__ float ex2(float x){ float r; asm("ex2.approx.ftz.f32 %0, %1;":"=f"(r):"f"(x)); return r; }
__device__ __forceinline__ float lg2(float x){ float r; asm("lg2.approx.f32 %0, %1;":"=f"(r):"f"(x)); return r; }
__device__ __forceinline__ u64 dup2(float x){ u64 r; asm("mov.b64 %0, {%1, %1};":"=l"(r):"f"(x)); return r; }
__device__ __forceinline__ u64 ffma2(u64 a, u64 b, u64 c){ u64 r; asm("fma.rn.f32x2 %0, %1, %2, %3;":"=l"(r):"l"(a),"l"(b),"l"(c)); return r; }
__device__ __forceinline__ void unpk(u64 v, float& lo, float& hi){ asm("mov.b64 {%0, %1}, %2;":"=f"(lo),"=f"(hi):"l"(v)); }

__global__ void prep_kernel(const float* __restrict__ p1, const float* __restrict__ p2) {
    int i = blockIdx.x * blockDim.x + threadIdx.x;   // pair index
    if (i >= NTOT/2) return;
    int j0 = 2*i, j1 = 2*i + 1;
    float x0 = p1[3*j0], y0 = p1[3*j0+1], z0 = p1[3*j0+2];
    float x1 = p1[3*j1], y1 = p1[3*j1+1], z1 = p1[3*j1+2];
    float w0 = 0.5f*(x0*x0+y0*y0+z0*z0), w1 = 0.5f*(x1*x1+y1*y1+z1*z1);
    d_X4[j0] = make_float4(x0,y0,z0,w0);
    d_X4[j1] = make_float4(x1,y1,z1,w1);
    d_cA[0][i] = make_float4(x0,x1,y0,y1);
    d_cB[0][i] = make_float4(z0,z1,-w0,-w1);
    x0 = p2[3*j0]; y0 = p2[3*j0+1]; z0 = p2[3*j0+2];
    x1 = p2[3*j1]; y1 = p2[3*j1+1]; z1 = p2[3*j1+2];
    w0 = 0.5f*(x0*x0+y0*y0+z0*z0); w1 = 0.5f*(x1*x1+y1*y1+z1*z1);
    d_Y4[j0] = make_float4(x0,y0,z0,w0);
    d_Y4[j1] = make_float4(x1,y1,z1,w1);
    d_cA[1][i] = make_float4(x0,x1,y0,y1);
    d_cB[1][i] = make_float4(z0,z1,-w0,-w1);
    d_pots[0][0][j0]=0.f; d_pots[0][1][j0]=0.f; d_pots[0][2][j0]=0.f; d_pots[0][3][j0]=0.f;
    d_pots[0][0][j1]=0.f; d_pots[0][1][j1]=0.f; d_pots[0][2][j1]=0.f; d_pots[0][3][j1]=0.f;
}

#define RPW 4           // rows per warp
#define WARPS 8
#define RPB (RPW*WARPS) // 32 rows per block

// softmin over columns with f32x2-packed inner loop (2 columns per lane-op):
//   t_ij = (h_j - 0.5|y_j|^2 - eps*logw) + x_i . y_j       (natural units)
//   softmin_i = 0.5|x_i|^2 - m_i - eps * ln( sum_j exp((t_ij - m_i)/eps) )
__global__ __launch_bounds__(256) void iter_kernel(float eps, int inbuf, int avg) {
    __shared__ float4 shA[NPAIR];   // (x0,x1,y0,y1) per column-pair
    __shared__ float4 shB[NPAIR];   // (z0,z1,w'0,w'1)
    int task = blockIdx.z, b = blockIdx.y;
    int ob = inbuf ^ 1;
    const float4* rows; const float4* cA; const float4* cB;
    const float* colpot; const float* rowold; float* outp;
    if (task == 0)      { rows = d_X4; cA = d_cA[1]; cB = d_cB[1]; colpot = d_pots[inbuf][1]; rowold = d_pots[inbuf][0]; outp = d_pots[ob][0]; }
    else if (task == 1) { rows = d_Y4; cA = d_cA[0]; cB = d_cB[0]; colpot = d_pots[inbuf][0]; rowold = d_pots[inbuf][1]; outp = d_pots[ob][1]; }
    else if (task == 2) { rows = d_X4; cA = d_cA[0]; cB = d_cB[0]; colpot = d_pots[inbuf][2]; rowold = d_pots[inbuf][2]; outp = d_pots[ob][2]; }
    else                { rows = d_Y4; cA = d_cA[1]; cB = d_cB[1]; colpot = d_pots[inbuf][3]; rowold = d_pots[inbuf][3]; outp = d_pots[ob][3]; }
    rows += b*NPTS; cA += b*NPAIR; cB += b*NPAIR; colpot += b*NPTS; rowold += b*NPTS; outp += b*NPTS;

    float eps_logw = eps * LOGW;
    for (int k = threadIdx.x; k < NPAIR; k += 256) {
        shA[k] = cA[k];
        float4 zb = cB[k];
        float p0 = colpot[2*k], p1 = colpot[2*k+1];
        shB[k] = make_float4(zb.x, zb.y, p0 + zb.z - eps_logw, p1 + zb.w - eps_logw);
    }
    __syncthreads();

    int warp = threadIdx.x >> 5, lane = threadIdx.x & 31;
    int row0 = blockIdx.x * RPB + warp * RPW;

    u64 rx2[RPW], ry2[RPW], rz2[RPW];
    float rw[RPW];
#pragma unroll
    for (int r = 0; r < RPW; r++) {
        float4 xr = rows[row0 + r];
        rx2[r] = dup2(xr.x); ry2[r] = dup2(xr.y); rz2[r] = dup2(xr.z);
        rw[r] = xr.w;
    }

    const ulonglong2* sA = (const ulonglong2*)shA;
    const ulonglong2* sB = (const ulonglong2*)shB;

    // pass 1: row max (two running maxima per row; FMAX rides the alu pipe)
    float mlo[RPW], mhi[RPW];
#pragma unroll
    for (int r = 0; r < RPW; r++) { mlo[r] = -3.4e38f; mhi[r] = -3.4e38f; }
#pragma unroll 2
    for (int k = lane; k < NPAIR; k += 32) {
        ulonglong2 ab = sA[k];        // .x = x-pair, .y = y-pair
        ulonglong2 zw = sB[k];        // .x = z-pair, .y = w'-pair
#pragma unroll
        for (int r = 0; r < RPW; r++) {
            u64 t2 = ffma2(rz2[r], zw.x, zw.y);
            t2 = ffma2(ry2[r], ab.y, t2);
            t2 = ffma2(rx2[r], ab.x, t2);
            float lo, hi; unpk(t2, lo, hi);
            mlo[r] = fmaxf(mlo[r], lo);
            mhi[r] = fmaxf(mhi[r], hi);
        }
    }
    float m[RPW];
#pragma unroll
    for (int r = 0; r < RPW; r++) m[r] = fmaxf(mlo[r], mhi[r]);
#pragma unroll
    for (int off = 16; off; off >>= 1)
#pragma unroll
        for (int r = 0; r < RPW; r++)
            m[r] = fmaxf(m[r], __shfl_xor_sync(0xffffffffu, m[r], off));

    // pass 2: sum of exp
    float kk = LOG2E / eps;
    u64 kk2 = dup2(kk);
    u64 mk2[RPW];
    float slo[RPW], shi[RPW];
#pragma unroll
    for (int r = 0; r < RPW; r++) { mk2[r] = dup2(-m[r] * kk); slo[r] = 0.f; shi[r] = 0.f; }
#pragma unroll 2
    for (int k = lane; k < NPAIR; k += 32) {
        ulonglong2 ab = sA[k];
        ulonglong2 zw = sB[k];
#pragma unroll
        for (int r = 0; r < RPW; r++) {
            u64 t2 = ffma2(rz2[r], zw.x, zw.y);
            t2 = ffma2(ry2[r], ab.y, t2);
            t2 = ffma2(rx2[r], ab.x, t2);
            u64 u2 = ffma2(t2, kk2, mk2[r]);
            float lo, hi; unpk(u2, lo, hi);
            slo[r] += ex2(lo);
            shi[r] += ex2(hi);
        }
    }
    float s[RPW];
#pragma unroll
    for (int r = 0; r < RPW; r++) s[r] = slo[r] + shi[r];
#pragma unroll
    for (int off = 16; off; off >>= 1)
#pragma unroll
        for (int r = 0; r < RPW; r++)
            s[r] += __shfl_xor_sync(0xffffffffu, s[r], off);

    if (lane < RPW) {
        int r = lane;
        int row = row0 + r;
        float sm = rw[r] - m[r] - eps * (lg2(s[r]) * LN2);
        outp[row] = avg ? 0.5f * (rowold[row] + sm) : sm;
    }
}

__global__ void reduce_kernel(int buf, float* __restrict__ out) {
    __shared__ float red[256];
    float acc = 0.f;
    for (int i = threadIdx.x; i < NTOT; i += 256) {
        acc += (d_pots[buf][0][i] - d_pots[buf][2][i])
             + (d_pots[buf][1][i] - d_pots[buf][3][i]);
    }
    red[threadIdx.x] = acc;
    __syncthreads();
    for (int off = 128; off; off >>= 1) {
        if (threadIdx.x < off) red[threadIdx.x] += red[threadIdx.x + off];
        __syncthreads();
    }
    if (threadIdx.x == 0) out[0] = red[0] / (float)NTOT;
}

extern "C" void kernel_launch(void* const* d_in, const int* in_sizes, int n_in,
                              void* d_out, int out_size) {
    const float* p1 = (const float*)d_in[0];
    const float* p2 = (const float*)d_in[1];
    float* out = (float*)d_out;

    // epsilon schedule: anneal in f64 (python-float semantics), square in f32
    float eps[128]; int n = 0;
    double sc = 8.0;
    while (sc > 0.01 && n < 120) { float f = (float)sc; eps[n++] = f * f; sc *= 0.9; }
    { float f = 0.01f; eps[n++] = f * f; }

    prep_kernel<<<(NTOT/2 + 255) / 256, 256>>>(p1, p2);

    int inbuf = 0;
    dim3 grid(NPTS / RPB, B, 4);
    for (int k = 0; k < n; k++) {
        iter_kernel<<<grid, 256>>>(eps[k], inbuf, 1);
        inbuf ^= 1;
    }
    // final extrapolation at target eps, no averaging
    iter_kernel<<<grid, 256>>>(eps[n - 1], inbuf, 0);
    reduce_kernel<<<1, 256>>>(inbuf ^ 1, out);
}

// round 3
// speedup vs baseline: 1.1613x; 1.0183x over previous
#include <cuda_runtime.h>

#define B 8
#define NPTS 2048
#define NPAIR (NPTS/2)
#define NTOT (B*NPTS)
#define LOGW 7.6246189861593985f   /* ln(2048) */
#define LOG2E 1.4426950408889634f
#define LN2 0.6931471805599453f

typedef unsigned long long u64;

__device__ float4 d_X4[NTOT];              // per-row coords (x,y,z, 0.5|p|^2)
__device__ float4 d_Y4[NTOT];
__device__ float4 d_cA[2][NTOT/2];         // pair-packed cols: (x0,x1,y0,y1)
__device__ float4 d_cB[2][NTOT/2];         // pair-packed cols: (z0,z1,-w0,-w1)
__device__ float d_pots[2][4][NTOT];       // [buffer][f,g,fx,gy][b*N+i]

__device__ __forceinline__ float lg2(float x){ float r; asm("lg2.approx.f32 %0, %1;":"=f"(r):"f"(x)); return r; }
__device__ __forceinline__ u64 dup2(float x){ u64 r; asm("mov.b64 %0, {%1, %1};":"=l"(r):"f"(x)); return r; }
__device__ __forceinline__ u64 ffma2(u64 a, u64 b, u64 c){ u64 r; asm("fma.rn.f32x2 %0, %1, %2, %3;":"=l"(r):"l"(a),"l"(b),"l"(c)); return r; }
__device__ __forceinline__ u64 fadd2(u64 a, u64 b){ u64 r; asm("add.rn.f32x2 %0, %1, %2;":"=l"(r):"l"(a),"l"(b)); return r; }
__device__ __forceinline__ void unpk(u64 v, float& lo, float& hi){ asm("mov.b64 {%0, %1}, %2;":"=f"(lo),"=f"(hi):"l"(v)); }
// packed exp2 on both halves; movs coalesce into register-pair allocation
__device__ __forceinline__ u64 ex2pair(u64 a){
    u64 r;
    asm("{\n\t.reg .f32 lo, hi, el, eh;\n\t"
        "mov.b64 {lo, hi}, %1;\n\t"
        "ex2.approx.ftz.f32 el, lo;\n\t"
        "ex2.approx.ftz.f32 eh, hi;\n\t"
        "mov.b64 %0, {el, eh};\n\t}"
        : "=l"(r) : "l"(a));
    return r;
}

__global__ void prep_kernel(const float* __restrict__ p1, const float* __restrict__ p2) {
    int i = blockIdx.x * blockDim.x + threadIdx.x;   // pair index
    if (i >= NTOT/2) return;
    int j0 = 2*i, j1 = 2*i + 1;
    float x0 = p1[3*j0], y0 = p1[3*j0+1], z0 = p1[3*j0+2];
    float x1 = p1[3*j1], y1 = p1[3*j1+1], z1 = p1[3*j1+2];
    float w0 = 0.5f*(x0*x0+y0*y0+z0*z0), w1 = 0.5f*(x1*x1+y1*y1+z1*z1);
    d_X4[j0] = make_float4(x0,y0,z0,w0);
    d_X4[j1] = make_float4(x1,y1,z1,w1);
    d_cA[0][i] = make_float4(x0,x1,y0,y1);
    d_cB[0][i] = make_float4(z0,z1,-w0,-w1);
    x0 = p2[3*j0]; y0 = p2[3*j0+1]; z0 = p2[3*j0+2];
    x1 = p2[3*j1]; y1 = p2[3*j1+1]; z1 = p2[3*j1+2];
    w0 = 0.5f*(x0*x0+y0*y0+z0*z0); w1 = 0.5f*(x1*x1+y1*y1+z1*z1);
    d_Y4[j0] = make_float4(x0,y0,z0,w0);
    d_Y4[j1] = make_float4(x1,y1,z1,w1);
    d_cA[1][i] = make_float4(x0,x1,y0,y1);
    d_cB[1][i] = make_float4(z0,z1,-w0,-w1);
    d_pots[0][0][j0]=0.f; d_pots[0][1][j0]=0.f; d_pots[0][2][j0]=0.f; d_pots[0][3][j0]=0.f;
    d_pots[0][0][j1]=0.f; d_pots[0][1][j1]=0.f; d_pots[0][2][j1]=0.f; d_pots[0][3][j1]=0.f;
}

#define RPW 8           // rows per warp
#define WARPS 8
#define RPB (RPW*WARPS) // 64 rows per block

// softmin over columns; f32x2-packed inner loop, 8 rows per warp.
//   t_ij = (h_j - 0.5|y_j|^2 - eps*logw) + x_i . y_j       (natural units)
//   softmin_i = 0.5|x_i|^2 - m_i - eps * ln( sum_j exp((t_ij - m_i)/eps) )
__global__ __launch_bounds__(256) void iter_kernel(float eps, int inbuf, int avg) {
    __shared__ float4 shA[NPAIR];   // (x0,x1,y0,y1) per column-pair
    __shared__ float4 shB[NPAIR];   // (z0,z1,w'0,w'1)
    int task = blockIdx.z, b = blockIdx.y;
    int ob = inbuf ^ 1;
    const float4* rows; const float4* cA; const float4* cB;
    const float* colpot; const float* rowold; float* outp;
    if (task == 0)      { rows = d_X4; cA = d_cA[1]; cB = d_cB[1]; colpot = d_pots[inbuf][1]; rowold = d_pots[inbuf][0]; outp = d_pots[ob][0]; }
    else if (task == 1) { rows = d_Y4; cA = d_cA[0]; cB = d_cB[0]; colpot = d_pots[inbuf][0]; rowold = d_pots[inbuf][1]; outp = d_pots[ob][1]; }
    else if (task == 2) { rows = d_X4; cA = d_cA[0]; cB = d_cB[0]; colpot = d_pots[inbuf][2]; rowold = d_pots[inbuf][2]; outp = d_pots[ob][2]; }
    else                { rows = d_Y4; cA = d_cA[1]; cB = d_cB[1]; colpot = d_pots[inbuf][3]; rowold = d_pots[inbuf][3]; outp = d_pots[ob][3]; }
    rows += b*NPTS; cA += b*NPAIR; cB += b*NPAIR; colpot += b*NPTS; rowold += b*NPTS; outp += b*NPTS;

    float eps_logw = eps * LOGW;
    for (int k = threadIdx.x; k < NPAIR; k += 256) {
        shA[k] = cA[k];
        float4 zb = cB[k];
        float p0 = colpot[2*k], p1 = colpot[2*k+1];
        shB[k] = make_float4(zb.x, zb.y, p0 + zb.z - eps_logw, p1 + zb.w - eps_logw);
    }
    __syncthreads();

    int warp = threadIdx.x >> 5, lane = threadIdx.x & 31;
    int row0 = blockIdx.x * RPB + warp * RPW;

    u64 rx2[RPW], ry2[RPW], rz2[RPW];
    float rw[RPW];
#pragma unroll
    for (int r = 0; r < RPW; r++) {
        float4 xr = rows[row0 + r];
        rx2[r] = dup2(xr.x); ry2[r] = dup2(xr.y); rz2[r] = dup2(xr.z);
        rw[r] = xr.w;
    }

    const ulonglong2* sA = (const ulonglong2*)shA;
    const ulonglong2* sB = (const ulonglong2*)shB;

    // pass 1: row max (two running maxima per row; FMAX rides the alu pipe)
    float mlo[RPW], mhi[RPW];
#pragma unroll
    for (int r = 0; r < RPW; r++) { mlo[r] = -3.4e38f; mhi[r] = -3.4e38f; }
#pragma unroll 2
    for (int k = lane; k < NPAIR; k += 32) {
        ulonglong2 ab = sA[k];        // .x = x-pair, .y = y-pair
        ulonglong2 zw = sB[k];        // .x = z-pair, .y = w'-pair
#pragma unroll
        for (int r = 0; r < RPW; r++) {
            u64 t2 = ffma2(rz2[r], zw.x, zw.y);
            t2 = ffma2(ry2[r], ab.y, t2);
            t2 = ffma2(rx2[r], ab.x, t2);
            float lo, hi; unpk(t2, lo, hi);
            mlo[r] = fmaxf(mlo[r], lo);
            mhi[r] = fmaxf(mhi[r], hi);
        }
    }
    float m[RPW];
#pragma unroll
    for (int r = 0; r < RPW; r++) m[r] = fmaxf(mlo[r], mhi[r]);
#pragma unroll
    for (int off = 16; off; off >>= 1)
#pragma unroll
        for (int r = 0; r < RPW; r++)
            m[r] = fmaxf(m[r], __shfl_xor_sync(0xffffffffu, m[r], off));

    // pass 2: sum of exp (packed accumulators, packed exp2)
    float kk = LOG2E / eps;
    u64 kk2 = dup2(kk);
    u64 mk2[RPW];
    u64 s2[RPW];
#pragma unroll
    for (int r = 0; r < RPW; r++) { mk2[r] = dup2(-m[r] * kk); s2[r] = 0; }
#pragma unroll 2
    for (int k = lane; k < NPAIR; k += 32) {
        ulonglong2 ab = sA[k];
        ulonglong2 zw = sB[k];
#pragma unroll
        for (int r = 0; r < RPW; r++) {
            u64 t2 = ffma2(rz2[r], zw.x, zw.y);
            t2 = ffma2(ry2[r], ab.y, t2);
            t2 = ffma2(rx2[r], ab.x, t2);
            u64 u2 = ffma2(t2, kk2, mk2[r]);
            s2[r] = fadd2(s2[r], ex2pair(u2));
        }
    }
    float s[RPW];
#pragma unroll
    for (int r = 0; r < RPW; r++) {
        float lo, hi; unpk(s2[r], lo, hi);
        s[r] = lo + hi;
    }
#pragma unroll
    for (int off = 16; off; off >>= 1)
#pragma unroll
        for (int r = 0; r < RPW; r++)
            s[r] += __shfl_xor_sync(0xffffffffu, s[r], off);

    if (lane < RPW) {
        int r = lane;
        int row = row0 + r;
        float mm = __shfl_sync(0xffffffffu, m[0], 0);  // placeholder avoided; use per-r values below
        (void)mm;
        float mr, sr, rwr;
        // lane r owns row r: pull its own registers
        mr = m[r]; sr = s[r]; rwr = rw[r];
        float sm = rwr - mr - eps * (lg2(sr) * LN2);
        outp[row] = avg ? 0.5f * (rowold[row] + sm) : sm;
    }
}

__global__ void reduce_kernel(int buf, float* __restrict__ out) {
    __shared__ float red[256];
    float acc = 0.f;
    for (int i = threadIdx.x; i < NTOT; i += 256) {
        acc += (d_pots[buf][0][i] - d_pots[buf][2][i])
             + (d_pots[buf][1][i] - d_pots[buf][3][i]);
    }
    red[threadIdx.x] = acc;
    __syncthreads();
    for (int off = 128; off; off >>= 1) {
        if (threadIdx.x < off) red[threadIdx.x] += red[threadIdx.x + off];
        __syncthreads();
    }
    if (threadIdx.x == 0) out[0] = red[0] / (float)NTOT;
}

extern "C" void kernel_launch(void* const* d_in, const int* in_sizes, int n_in,
                              void* d_out, int out_size) {
    const float* p1 = (const float*)d_in[0];
    const float* p2 = (const float*)d_in[1];
    float* out = (float*)d_out;

    // epsilon schedule: anneal in f64 (python-float semantics), square in f32
    float eps[128]; int n = 0;
    double sc = 8.0;
    while (sc > 0.01 && n < 120) { float f = (float)sc; eps[n++] = f * f; sc *= 0.9; }
    { float f = 0.01f; eps[n++] = f * f; }

    prep_kernel<<<(NTOT/2 + 255) / 256, 256>>>(p1, p2);

    int inbuf = 0;
    dim3 grid(NPTS / RPB, B, 4);
    for (int k = 0; k < n; k++) {
        iter_kernel<<<grid, 256>>>(eps[k], inbuf, 1);
        inbuf ^= 1;
    }
    // final extrapolation at target eps, no averaging
    iter_kernel<<<grid, 256>>>(eps[n - 1], inbuf, 0);
    reduce_kernel<<<1, 256>>>(inbuf ^ 1, out);
}

// round 4
// speedup vs baseline: 1.6565x; 1.4264x over previous
#include <cuda_runtime.h>

#define B 8
#define NPTS 2048
#define NPAIR (NPTS/2)
#define NTOT (B*NPTS)
#define LOGW 7.6246189861593985f   /* ln(2048) */
#define LOG2E 1.4426950408889634f
#define LN2 0.6931471805599453f

typedef unsigned long long u64;

__device__ float4 d_X4[NTOT];              // per-row coords (x,y,z, 0.5|p|^2)
__device__ float4 d_Y4[NTOT];
__device__ float4 d_cA[2][NTOT/2];         // pair-packed cols: (x0,x1,y0,y1)
__device__ float4 d_cB[2][NTOT/2];         // pair-packed cols: (z0,z1,-w0,-w1)
__device__ float d_pots[2][4][NTOT];       // [buffer][f,g,fx,gy][b*N+i]
__device__ float d_mprev[4][NTOT];         // per-task row-max estimate (= w - softmin_raw)

__device__ __forceinline__ float lg2(float x){ float r; asm("lg2.approx.f32 %0, %1;":"=f"(r):"f"(x)); return r; }
__device__ __forceinline__ u64 dup2(float x){ u64 r; asm("mov.b64 %0, {%1, %1};":"=l"(r):"f"(x)); return r; }
__device__ __forceinline__ u64 ffma2(u64 a, u64 b, u64 c){ u64 r; asm("fma.rn.f32x2 %0, %1, %2, %3;":"=l"(r):"l"(a),"l"(b),"l"(c)); return r; }
__device__ __forceinline__ u64 fadd2(u64 a, u64 b){ u64 r; asm("add.rn.f32x2 %0, %1, %2;":"=l"(r):"l"(a),"l"(b)); return r; }
__device__ __forceinline__ void unpk(u64 v, float& lo, float& hi){ asm("mov.b64 {%0, %1}, %2;":"=f"(lo),"=f"(hi):"l"(v)); }
__device__ __forceinline__ u64 ex2pair(u64 a){
    u64 r;
    asm("{\n\t.reg .f32 lo, hi, el, eh;\n\t"
        "mov.b64 {lo, hi}, %1;\n\t"
        "ex2.approx.ftz.f32 el, lo;\n\t"
        "ex2.approx.ftz.f32 eh, hi;\n\t"
        "mov.b64 %0, {el, eh};\n\t}"
        : "=l"(r) : "l"(a));
    return r;
}

__global__ void prep_kernel(const float* __restrict__ p1, const float* __restrict__ p2) {
    int i = blockIdx.x * blockDim.x + threadIdx.x;   // pair index
    if (i >= NTOT/2) return;
    int j0 = 2*i, j1 = 2*i + 1;
    float x0 = p1[3*j0], y0 = p1[3*j0+1], z0 = p1[3*j0+2];
    float x1 = p1[3*j1], y1 = p1[3*j1+1], z1 = p1[3*j1+2];
    float w0 = 0.5f*(x0*x0+y0*y0+z0*z0), w1 = 0.5f*(x1*x1+y1*y1+z1*z1);
    d_X4[j0] = make_float4(x0,y0,z0,w0);
    d_X4[j1] = make_float4(x1,y1,z1,w1);
    d_cA[0][i] = make_float4(x0,x1,y0,y1);
    d_cB[0][i] = make_float4(z0,z1,-w0,-w1);
    x0 = p2[3*j0]; y0 = p2[3*j0+1]; z0 = p2[3*j0+2];
    x1 = p2[3*j1]; y1 = p2[3*j1+1]; z1 = p2[3*j1+2];
    w0 = 0.5f*(x0*x0+y0*y0+z0*z0); w1 = 0.5f*(x1*x1+y1*y1+z1*z1);
    d_Y4[j0] = make_float4(x0,y0,z0,w0);
    d_Y4[j1] = make_float4(x1,y1,z1,w1);
    d_cA[1][i] = make_float4(x0,x1,y0,y1);
    d_cB[1][i] = make_float4(z0,z1,-w0,-w1);
    d_pots[0][0][j0]=0.f; d_pots[0][1][j0]=0.f; d_pots[0][2][j0]=0.f; d_pots[0][3][j0]=0.f;
    d_pots[0][0][j1]=0.f; d_pots[0][1][j1]=0.f; d_pots[0][2][j1]=0.f; d_pots[0][3][j1]=0.f;
}

#define RPW 4           // rows per warp
#define WARPS 4
#define TPB (WARPS*32)  // 128 threads
#define RPB (RPW*WARPS) // 16 rows per block

// Single-pass softmin using previous iteration's max estimate.
//   t_ij = (h_j - 0.5|y_j|^2 - eps*logw) + x_i . y_j
//   softmin_i = 0.5|x_i|^2 - m - eps*ln( sum_j exp((t_ij - m)/eps) )   (exact for any safe m)
// Safety: if the row sum over/underflows, recompute max and resum (cold path).
__global__ __launch_bounds__(TPB) void iter_kernel(float eps, int inbuf, int avg, int first) {
    __shared__ float4 shA[NPAIR];   // (x0,x1,y0,y1)
    __shared__ float4 shB[NPAIR];   // (z0,z1,w'0,w'1)
    int task = blockIdx.z, b = blockIdx.y;
    int ob = inbuf ^ 1;
    const float4* rows; const float4* cA; const float4* cB;
    const float* colpot; const float* rowold; float* outp;
    if (task == 0)      { rows = d_X4; cA = d_cA[1]; cB = d_cB[1]; colpot = d_pots[inbuf][1]; rowold = d_pots[inbuf][0]; outp = d_pots[ob][0]; }
    else if (task == 1) { rows = d_Y4; cA = d_cA[0]; cB = d_cB[0]; colpot = d_pots[inbuf][0]; rowold = d_pots[inbuf][1]; outp = d_pots[ob][1]; }
    else if (task == 2) { rows = d_X4; cA = d_cA[0]; cB = d_cB[0]; colpot = d_pots[inbuf][2]; rowold = d_pots[inbuf][2]; outp = d_pots[ob][2]; }
    else                { rows = d_Y4; cA = d_cA[1]; cB = d_cB[1]; colpot = d_pots[inbuf][3]; rowold = d_pots[inbuf][3]; outp = d_pots[ob][3]; }
    float* mprev = d_mprev[task] + b*NPTS;
    rows += b*NPTS; cA += b*NPAIR; cB += b*NPAIR; colpot += b*NPTS; rowold += b*NPTS; outp += b*NPTS;

    float eps_logw = eps * LOGW;
    for (int k = threadIdx.x; k < NPAIR; k += TPB) {
        shA[k] = cA[k];
        float4 zb = cB[k];
        float p0 = colpot[2*k], p1 = colpot[2*k+1];
        shB[k] = make_float4(zb.x, zb.y, p0 + zb.z - eps_logw, p1 + zb.w - eps_logw);
    }
    __syncthreads();

    int warp = threadIdx.x >> 5, lane = threadIdx.x & 31;
    int row0 = blockIdx.x * RPB + warp * RPW;

    float kk = LOG2E / eps;
    u64 kk2 = dup2(kk);

    u64 rx2[RPW], ry2[RPW], rz2[RPW], mk2[RPW], s2[RPW];
    float rw[RPW], m_used[RPW];
#pragma unroll
    for (int r = 0; r < RPW; r++) {
        float4 xr = rows[row0 + r];
        rx2[r] = dup2(xr.x); ry2[r] = dup2(xr.y); rz2[r] = dup2(xr.z);
        rw[r] = xr.w;
        float me = first ? 0.f : mprev[row0 + r];
        m_used[r] = me;
        mk2[r] = dup2(-me * kk);
        s2[r] = 0;
    }

    const ulonglong2* sA = (const ulonglong2*)shA;
    const ulonglong2* sB = (const ulonglong2*)shB;

#pragma unroll 4
    for (int k = lane; k < NPAIR; k += 32) {
        ulonglong2 ab = sA[k];        // x-pair, y-pair
        ulonglong2 zw = sB[k];        // z-pair, w'-pair
#pragma unroll
        for (int r = 0; r < RPW; r++) {
            u64 t2 = ffma2(rz2[r], zw.x, zw.y);
            t2 = ffma2(ry2[r], ab.y, t2);
            t2 = ffma2(rx2[r], ab.x, t2);
            u64 u2 = ffma2(t2, kk2, mk2[r]);
            s2[r] = fadd2(s2[r], ex2pair(u2));
        }
    }
    float s[RPW];
#pragma unroll
    for (int r = 0; r < RPW; r++) { float lo, hi; unpk(s2[r], lo, hi); s[r] = lo + hi; }
#pragma unroll
    for (int off = 16; off; off >>= 1)
#pragma unroll
        for (int r = 0; r < RPW; r++)
            s[r] += __shfl_xor_sync(0xffffffffu, s[r], off);

    // safety net: if estimate was too far off, recompute max + resum (cold)
    unsigned badmask = 0;
#pragma unroll
    for (int r = 0; r < RPW; r++)
        if (!(s[r] >= 1e-12f && s[r] <= 1e30f)) badmask |= 1u << r;
    if (__any_sync(0xffffffffu, badmask != 0)) {
        float mlo[RPW], mhi[RPW];
#pragma unroll
        for (int r = 0; r < RPW; r++) { mlo[r] = -3.4e38f; mhi[r] = -3.4e38f; }
        for (int k = lane; k < NPAIR; k += 32) {
            ulonglong2 ab = sA[k];
            ulonglong2 zw = sB[k];
#pragma unroll
            for (int r = 0; r < RPW; r++) {
                u64 t2 = ffma2(rz2[r], zw.x, zw.y);
                t2 = ffma2(ry2[r], ab.y, t2);
                t2 = ffma2(rx2[r], ab.x, t2);
                float lo, hi; unpk(t2, lo, hi);
                mlo[r] = fmaxf(mlo[r], lo);
                mhi[r] = fmaxf(mhi[r], hi);
            }
        }
        float mt[RPW];
#pragma unroll
        for (int r = 0; r < RPW; r++) mt[r] = fmaxf(mlo[r], mhi[r]);
#pragma unroll
        for (int off = 16; off; off >>= 1)
#pragma unroll
            for (int r = 0; r < RPW; r++)
                mt[r] = fmaxf(mt[r], __shfl_xor_sync(0xffffffffu, mt[r], off));
        u64 sb2[RPW], mkb[RPW];
#pragma unroll
        for (int r = 0; r < RPW; r++) { mkb[r] = dup2(-mt[r] * kk); sb2[r] = 0; }
        for (int k = lane; k < NPAIR; k += 32) {
            ulonglong2 ab = sA[k];
            ulonglong2 zw = sB[k];
#pragma unroll
            for (int r = 0; r < RPW; r++) {
                u64 t2 = ffma2(rz2[r], zw.x, zw.y);
                t2 = ffma2(ry2[r], ab.y, t2);
                t2 = ffma2(rx2[r], ab.x, t2);
                u64 u2 = ffma2(t2, kk2, mkb[r]);
                sb2[r] = fadd2(sb2[r], ex2pair(u2));
            }
        }
        float sn[RPW];
#pragma unroll
        for (int r = 0; r < RPW; r++) { float lo, hi; unpk(sb2[r], lo, hi); sn[r] = lo + hi; }
#pragma unroll
        for (int off = 16; off; off >>= 1)
#pragma unroll
            for (int r = 0; r < RPW; r++)
                sn[r] += __shfl_xor_sync(0xffffffffu, sn[r], off);
#pragma unroll
        for (int r = 0; r < RPW; r++)
            if ((badmask >> r) & 1u) { s[r] = sn[r]; m_used[r] = mt[r]; }
    }

    if (lane < RPW) {
        int r = lane;
        int row = row0 + r;
        float sm = rw[r] - m_used[r] - eps * (lg2(s[r]) * LN2);
        outp[row] = avg ? 0.5f * (rowold[row] + sm) : sm;
        mprev[row] = rw[r] - sm;   // = m_used + eps*ln(s): next iter's max estimate
    }
}

__global__ void reduce_kernel(int buf, float* __restrict__ out) {
    __shared__ float red[256];
    float acc = 0.f;
    for (int i = threadIdx.x; i < NTOT; i += 256) {
        acc += (d_pots[buf][0][i] - d_pots[buf][2][i])
             + (d_pots[buf][1][i] - d_pots[buf][3][i]);
    }
    red[threadIdx.x] = acc;
    __syncthreads();
    for (int off = 128; off; off >>= 1) {
        if (threadIdx.x < off) red[threadIdx.x] += red[threadIdx.x + off];
        __syncthreads();
    }
    if (threadIdx.x == 0) out[0] = red[0] / (float)NTOT;
}

extern "C" void kernel_launch(void* const* d_in, const int* in_sizes, int n_in,
                              void* d_out, int out_size) {
    const float* p1 = (const float*)d_in[0];
    const float* p2 = (const float*)d_in[1];
    float* out = (float*)d_out;

    // epsilon schedule: anneal in f64 (python-float semantics), square in f32
    float eps[128]; int n = 0;
    double sc = 8.0;
    while (sc > 0.01 && n < 120) { float f = (float)sc; eps[n++] = f * f; sc *= 0.9; }
    { float f = 0.01f; eps[n++] = f * f; }

    prep_kernel<<<(NTOT/2 + 255) / 256, 256>>>(p1, p2);

    int inbuf = 0;
    dim3 grid(NPTS / RPB, B, 4);
    for (int k = 0; k < n; k++) {
        iter_kernel<<<grid, TPB>>>(eps[k], inbuf, 1, k == 0);
        inbuf ^= 1;
    }
    // final extrapolation at target eps, no averaging
    iter_kernel<<<grid, TPB>>>(eps[n - 1], inbuf, 0, 0);
    reduce_kernel<<<1, 256>>>(inbuf ^ 1, out);
}